// round 7
// baseline (speedup 1.0000x reference)
#include <cuda_runtime.h>
#include <cstdint>

#define BATCH 2
#define SEQ 4096
#define NH 16
#define DK 64
#define DM 1024
#define L2E 1.4426950408889634f

// ---------------- scratch (no allocation allowed) ----------------
__device__ float g_Q[(size_t)BATCH * NH * SEQ * DK];
__device__ float g_K[(size_t)BATCH * NH * SEQ * DK];
__device__ float g_V[(size_t)BATCH * NH * SEQ * DK];
__device__ float g_A[(size_t)BATCH * SEQ * DM];
__device__ float g_Xr[(size_t)BATCH * SEQ * DM];   // tf32-rounded x
__device__ float g_Wr[(size_t)4 * DM * DM];        // tf32-rounded Wq,Wk,Wv,Wo

// ---------------- helpers ----------------
__device__ __forceinline__ uint32_t f2tf(float x) {
    uint32_t r;
    asm("cvt.rna.tf32.f32 %0, %1;" : "=r"(r) : "f"(x));
    return r;
}
__device__ __forceinline__ float f2tff(float x) {
    return __uint_as_float(f2tf(x));
}
__device__ __forceinline__ uint32_t smem_u32(const void* p) {
    uint32_t a;
    asm("{ .reg .u64 t; cvta.to.shared.u64 t, %1; cvt.u32.u64 %0, t; }"
        : "=r"(a) : "l"(p));
    return a;
}
__device__ __forceinline__ void cp16(uint32_t dst, const void* src) {
    asm volatile("cp.async.cg.shared.global [%0], [%1], 16;" :: "r"(dst), "l"(src));
}
__device__ __forceinline__ void cp_commit() {
    asm volatile("cp.async.commit_group;" ::: "memory");
}
template <int N>
__device__ __forceinline__ void cp_wait() {
    asm volatile("cp.async.wait_group %0;" :: "n"(N) : "memory");
}
__device__ __forceinline__ void mma_tf32(float c[4], uint32_t a0, uint32_t a1,
                                         uint32_t a2, uint32_t a3,
                                         uint32_t b0, uint32_t b1) {
    asm volatile(
        "mma.sync.aligned.m16n8k8.row.col.f32.tf32.tf32.f32 "
        "{%0,%1,%2,%3}, {%4,%5,%6,%7}, {%8,%9}, {%0,%1,%2,%3};"
        : "+f"(c[0]), "+f"(c[1]), "+f"(c[2]), "+f"(c[3])
        : "r"(a0), "r"(a1), "r"(a2), "r"(a3), "r"(b0), "r"(b1));
}

// ---------------- pre-round x + all W to tf32 (rna) ----------------
__global__ __launch_bounds__(256) void round_tf32_kernel(
    const float* __restrict__ x, const float* __restrict__ Wq,
    const float* __restrict__ Wk, const float* __restrict__ Wv,
    const float* __restrict__ Wo) {
    size_t i4 = (size_t)blockIdx.x * 256 + threadIdx.x;  // float4 index
    const float4* src;
    float4* dst;
    if (i4 < 2097152) {
        src = (const float4*)x + i4;
        dst = (float4*)g_Xr + i4;
    } else {
        size_t r = i4 - 2097152;
        int j = (int)(r >> 18);
        size_t o = r & 262143;
        const float* w = (j == 0) ? Wq : (j == 1) ? Wk : (j == 2) ? Wv : Wo;
        src = (const float4*)w + o;
        dst = (float4*)g_Wr + (size_t)j * 262144 + o;
    }
    float4 v = *src;
    float4 u;
    u.x = f2tff(v.x); u.y = f2tff(v.y); u.z = f2tff(v.z); u.w = f2tff(v.w);
    *dst = u;
}

// ---------------- mma.sync tf32 GEMM, padded smem, 2-stage cp.async -------
// C = A(Mx1024) * W(1024x1024)^T, tile 128x128, 256 thr, warp tile 64x32.
// Inputs pre-rounded tf32.  Padded stride 36 (u32): bank = (4r+k)&31, clean.
// MODE 0: row-major fp32 C.  MODE 1: scatter [b][h][s][64], tf32-rounded.
#define GSTAGE_BYTES 36864          // A 128x36 u32 (18432B) + W 128x36 u32
#define GEMM_SMEM (2 * GSTAGE_BYTES)

template <int MODE>
__global__ __launch_bounds__(256, 2) void gemm_mma(
    const float* __restrict__ Abase, const float* __restrict__ Wbase,
    float* __restrict__ C0, float* __restrict__ C1, float* __restrict__ C2) {
    extern __shared__ __align__(16) char smraw[];
    const uint32_t smb = smem_u32(smraw);

    const int tid = threadIdx.x, wid = tid >> 5, lane = tid & 31;
    const int g = lane >> 2, tig = lane & 3;
    const int wm = (wid & 1) * 64, wn = (wid >> 1) * 32;
    const int z = blockIdx.z;
    const int m0 = blockIdx.y * 128, n0 = blockIdx.x * 128;
    const float* W = Wbase + (size_t)z * (DM * DM);
    float* C = (z == 0) ? C0 : (z == 1) ? C1 : C2;

    float acc[4][4][4];
#pragma unroll
    for (int mt = 0; mt < 4; mt++)
#pragma unroll
        for (int nt = 0; nt < 4; nt++)
#pragma unroll
            for (int k = 0; k < 4; k++) acc[mt][nt][k] = 0.f;

    const int lr = tid >> 3, lc = (tid & 7) * 4;  // row, k-col(4) for fills

    auto fill = [&](int s) {
        const uint32_t st = smb + (uint32_t)(s & 1) * GSTAGE_BYTES;
        const int kb = s * 32;
        // A: 128 rows x 32 k ; each thread: 4 chunks (rows lr, lr+32, lr+64, lr+96)
#pragma unroll
        for (int i = 0; i < 4; i++) {
            int r = lr + i * 32;
            cp16(st + (r * 36 + lc) * 4, Abase + (size_t)(m0 + r) * DM + kb + lc);
        }
#pragma unroll
        for (int i = 0; i < 4; i++) {
            int r = lr + i * 32;
            cp16(st + 18432 * 4 / 4 * 4 + (r * 36 + lc) * 4 - 18432 * 3,  // placeholder
                 nullptr);
        }
        cp_commit();
    };
    (void)fill;  // replaced below (explicit, no lambda tricks)

    auto fill2 = [&](int s) {
        const uint32_t st = smb + (uint32_t)(s & 1) * GSTAGE_BYTES;
        const int kb = s * 32;
#pragma unroll
        for (int i = 0; i < 4; i++) {
            int r = lr + i * 32;
            cp16(st + (r * 36 + lc) * 4, Abase + (size_t)(m0 + r) * DM + kb + lc);
        }
#pragma unroll
        for (int i = 0; i < 4; i++) {
            int r = lr + i * 32;
            cp16(st + 18432 + (r * 36 + lc) * 4,
                 W + (size_t)(n0 + r) * DM + kb + lc);
        }
        cp_commit();
    };

    fill2(0);

    for (int s = 0; s < 32; s++) {
        if (s + 1 < 32) {
            fill2(s + 1);
            cp_wait<1>();
        } else {
            cp_wait<0>();
        }
        __syncthreads();
        const uint32_t* As = (const uint32_t*)(smraw + (size_t)(s & 1) * GSTAGE_BYTES);
        const uint32_t* Ws = As + 4608;  // 18432 B

#pragma unroll
        for (int kk = 0; kk < 32; kk += 8) {
            uint32_t a[4][4], b[4][2];
#pragma unroll
            for (int mt = 0; mt < 4; mt++) {
                int r = wm + mt * 16;
                a[mt][0] = As[(r + g) * 36 + kk + tig];
                a[mt][1] = As[(r + g + 8) * 36 + kk + tig];
                a[mt][2] = As[(r + g) * 36 + kk + tig + 4];
                a[mt][3] = As[(r + g + 8) * 36 + kk + tig + 4];
            }
#pragma unroll
            for (int nt = 0; nt < 4; nt++) {
                int cn = wn + nt * 8 + g;
                b[nt][0] = Ws[cn * 36 + kk + tig];
                b[nt][1] = Ws[cn * 36 + kk + tig + 4];
            }
#pragma unroll
            for (int mt = 0; mt < 4; mt++)
#pragma unroll
                for (int nt = 0; nt < 4; nt++)
                    mma_tf32(acc[mt][nt], a[mt][0], a[mt][1], a[mt][2], a[mt][3],
                             b[nt][0], b[nt][1]);
        }
        __syncthreads();
    }

#pragma unroll
    for (int mt = 0; mt < 4; mt++) {
#pragma unroll
        for (int nt = 0; nt < 4; nt++) {
            int r0 = m0 + wm + mt * 16 + g;
            int r1 = r0 + 8;
            int cc = n0 + wn + nt * 8 + 2 * tig;
            if (MODE == 0) {
                *(float2*)&C[(size_t)r0 * DM + cc] =
                    make_float2(acc[mt][nt][0], acc[mt][nt][1]);
                *(float2*)&C[(size_t)r1 * DM + cc] =
                    make_float2(acc[mt][nt][2], acc[mt][nt][3]);
            } else {
                int h = cc >> 6, d = cc & 63;
                int b0i = r0 >> 12, s0 = r0 & (SEQ - 1);
                int b1i = r1 >> 12, s1 = r1 & (SEQ - 1);
                *(float2*)&C[((size_t)(b0i * NH + h) * SEQ + s0) * DK + d] =
                    make_float2(f2tff(acc[mt][nt][0]), f2tff(acc[mt][nt][1]));
                *(float2*)&C[((size_t)(b1i * NH + h) * SEQ + s1) * DK + d] =
                    make_float2(f2tff(acc[mt][nt][2]), f2tff(acc[mt][nt][3]));
            }
        }
    }
}

// ---------------- RoPE (in-place; folds Q-scale; rounds to tf32) ----------
__global__ void rope_kernel(float* __restrict__ Q, float* __restrict__ K,
                            const int* __restrict__ pos) {
    const int NPAIR = BATCH * NH * SEQ * (DK / 2);
    int i = blockIdx.x * blockDim.x + threadIdx.x;
    if (i >= NPAIR) return;
    int j = i & 31;
    int s = (i >> 5) & (SEQ - 1);
    int h = (i >> 17) & (NH - 1);
    int b = i >> 21;

    const bool isQ = (blockIdx.y == 0);
    float* ptr = isQ ? Q : K;
    int p = pos[b * SEQ + s];
    float freq = exp2f(-(float)j * (13.287712379549449f / 32.f));
    float ang = (float)p * freq;
    float sn, cs;
    sincosf(ang, &sn, &cs);

    size_t basei = ((size_t)(b * NH + h) * SEQ + s) * DK + 2 * j;
    float e = ptr[basei];
    float o = ptr[basei + 1];
    float ne = e * cs - o * sn;
    float no = e * sn + o * cs;
    if (isQ) {
        const float qscale = 0.125f * L2E;
        ne *= qscale;
        no *= qscale;
    }
    ptr[basei] = f2tff(ne);
    ptr[basei + 1] = f2tff(no);
}

// ---------------- causal flash attention: Br=128, Bc=64, 8 warps ----------
// grid (32 q-tiles, 16 heads, 2 batch); 256 threads; 16 rows/warp.
// smem u32: Qs[128*68] | Ks0,Ks1[64*68] | Vs0,Vs1[64*72] | Ps[128*68]
#define QS_OFF 0
#define KS_OFF 8704
#define VS_OFF (8704 + 2 * 4352)
#define PS_OFF (8704 + 2 * 4352 + 2 * 4608)
#define ATT_SMEM ((8704 + 2 * 4352 + 2 * 4608 + 8704) * 4)

__global__ __launch_bounds__(256) void attn_tf32(const float* __restrict__ gQ,
                                                 const float* __restrict__ gK,
                                                 const float* __restrict__ gV,
                                                 float* __restrict__ gO) {
    extern __shared__ uint32_t sm[];
    uint32_t* Qs = sm + QS_OFF;
    uint32_t* Ps = sm + PS_OFF;
    const uint32_t smb = smem_u32(sm);

    const int qt = 31 - (int)blockIdx.x;   // big tiles first
    const int h = blockIdx.y;
    const int b = blockIdx.z;
    const int tid = threadIdx.x;
    const int wid = tid >> 5, lane = tid & 31;
    const int g = lane >> 2, tig = lane & 3;
    const int wr = wid * 16;

    const size_t bh = (size_t)(b * NH + h) * SEQ;
    const float* Qb = gQ + (bh + (size_t)qt * 128) * DK;
    const float* Kb = gK + bh * DK;
    const float* Vb = gV + bh * DK;

    // prefetch K/V tile kt into buffer buf
    auto prefetch = [&](int kt, int buf) {
        const uint32_t kst = smb + (KS_OFF + buf * 4352) * 4;
        const uint32_t vst = smb + (VS_OFF + buf * 4608) * 4;
#pragma unroll
        for (int i = 0; i < 4; i++) {  // K: 1024 chunks / 256 thr
            int q = tid + i * 256;
            int r = q >> 4, c = q & 15;
            cp16(kst + (r * 68 + c * 4) * 4,
                 Kb + (size_t)(kt * 64 + r) * DK + c * 4);
        }
#pragma unroll
        for (int i = 0; i < 4; i++) {  // V
            int q = tid + i * 256;
            int r = q >> 4, c = q & 15;
            cp16(vst + (r * 72 + c * 4) * 4,
                 Vb + (size_t)(kt * 64 + r) * DK + c * 4);
        }
        cp_commit();
    };

    // load Q tile (already scaled + tf32-rounded by rope): 2048 float4
#pragma unroll
    for (int p = 0; p < 8; p++) {
        int idx = p * 256 + tid;
        int r = idx >> 4, c4 = (idx & 15) * 4;
        float4 v = *(const float4*)(Qb + (size_t)r * DK + c4);
        uint32_t* qp = &Qs[r * 68 + c4];
        qp[0] = __float_as_uint(v.x); qp[1] = __float_as_uint(v.y);
        qp[2] = __float_as_uint(v.z); qp[3] = __float_as_uint(v.w);
    }

    prefetch(0, 0);

    float oacc[8][4];
    float m0 = -1e30f, m1 = -1e30f, l0 = 0.f, l1 = 0.f;
#pragma unroll
    for (int nt = 0; nt < 8; nt++)
#pragma unroll
        for (int k = 0; k < 4; k++) oacc[nt][k] = 0.f;

    const int ntiles = 2 * qt + 2;
    for (int kt = 0; kt < ntiles; kt++) {
        const int buf = kt & 1;
        __syncthreads();  // all warps done with buf (iter kt-2) & Q/Ps ready
        if (kt + 1 < ntiles) {
            prefetch(kt + 1, buf ^ 1);
            cp_wait<1>();
        } else {
            cp_wait<0>();
        }
        __syncthreads();  // buf kt visible

        const uint32_t* Ks = sm + KS_OFF + buf * 4352;
        const uint32_t* Vs = sm + VS_OFF + buf * 4608;

        float sacc[8][4];
#pragma unroll
        for (int nt = 0; nt < 8; nt++)
#pragma unroll
            for (int k = 0; k < 4; k++) sacc[nt][k] = 0.f;

#pragma unroll
        for (int kk = 0; kk < 64; kk += 8) {
            uint32_t a0 = Qs[(wr + g) * 68 + kk + tig];
            uint32_t a1 = Qs[(wr + g + 8) * 68 + kk + tig];
            uint32_t a2 = Qs[(wr + g) * 68 + kk + tig + 4];
            uint32_t a3 = Qs[(wr + g + 8) * 68 + kk + tig + 4];
#pragma unroll
            for (int nt = 0; nt < 8; nt++) {
                uint32_t b0 = Ks[(nt * 8 + g) * 68 + kk + tig];
                uint32_t b1 = Ks[(nt * 8 + g) * 68 + kk + tig + 4];
                mma_tf32(sacc[nt], a0, a1, a2, a3, b0, b1);
            }
        }

        if (kt >= 2 * qt) {  // diagonal region: mask col_global > row_global
            const int rbase = wr + g;        // local row (0..127)
            const int coff = (kt & 1) * 64;  // col offset within 128-wide diag
#pragma unroll
            for (int nt = 0; nt < 8; nt++) {
                int c0 = coff + nt * 8 + 2 * tig, c1 = c0 + 1;
                if (c0 > rbase) sacc[nt][0] = -1e30f;
                if (c1 > rbase) sacc[nt][1] = -1e30f;
                if (c0 > rbase + 8) sacc[nt][2] = -1e30f;
                if (c1 > rbase + 8) sacc[nt][3] = -1e30f;
            }
        }

        float tm0 = -1e30f, tm1 = -1e30f;
#pragma unroll
        for (int nt = 0; nt < 8; nt++) {
            tm0 = fmaxf(tm0, fmaxf(sacc[nt][0], sacc[nt][1]));
            tm1 = fmaxf(tm1, fmaxf(sacc[nt][2], sacc[nt][3]));
        }
        tm0 = fmaxf(tm0, __shfl_xor_sync(0xffffffffu, tm0, 1));
        tm0 = fmaxf(tm0, __shfl_xor_sync(0xffffffffu, tm0, 2));
        tm1 = fmaxf(tm1, __shfl_xor_sync(0xffffffffu, tm1, 1));
        tm1 = fmaxf(tm1, __shfl_xor_sync(0xffffffffu, tm1, 2));

        float mn0 = fmaxf(m0, tm0), mn1 = fmaxf(m1, tm1);
        float al0 = exp2f(m0 - mn0), al1 = exp2f(m1 - mn1);
        m0 = mn0; m1 = mn1;

        float rs0 = 0.f, rs1 = 0.f;
#pragma unroll
        for (int nt = 0; nt < 8; nt++) {
            sacc[nt][0] = exp2f(sacc[nt][0] - mn0);
            sacc[nt][1] = exp2f(sacc[nt][1] - mn0);
            sacc[nt][2] = exp2f(sacc[nt][2] - mn1);
            sacc[nt][3] = exp2f(sacc[nt][3] - mn1);
            rs0 += sacc[nt][0] + sacc[nt][1];
            rs1 += sacc[nt][2] + sacc[nt][3];
        }
        rs0 += __shfl_xor_sync(0xffffffffu, rs0, 1);
        rs0 += __shfl_xor_sync(0xffffffffu, rs0, 2);
        rs1 += __shfl_xor_sync(0xffffffffu, rs1, 1);
        rs1 += __shfl_xor_sync(0xffffffffu, rs1, 2);
        l0 = l0 * al0 + rs0;
        l1 = l1 * al1 + rs1;

#pragma unroll
        for (int nt = 0; nt < 8; nt++) {
            oacc[nt][0] *= al0; oacc[nt][1] *= al0;
            oacc[nt][2] *= al1; oacc[nt][3] *= al1;
        }

        // publish P (tf32) to this warp's 16 rows
#pragma unroll
        for (int nt = 0; nt < 8; nt++) {
            uint2 p0 = make_uint2(f2tf(sacc[nt][0]), f2tf(sacc[nt][1]));
            uint2 p1 = make_uint2(f2tf(sacc[nt][2]), f2tf(sacc[nt][3]));
            *(uint2*)&Ps[(wr + g) * 68 + nt * 8 + 2 * tig] = p0;
            *(uint2*)&Ps[(wr + g + 8) * 68 + nt * 8 + 2 * tig] = p1;
        }
        __syncwarp();

        // O += P V  (A-frags from own rows only)
#pragma unroll
        for (int kk = 0; kk < 64; kk += 8) {
            uint32_t a0 = Ps[(wr + g) * 68 + kk + tig];
            uint32_t a1 = Ps[(wr + g + 8) * 68 + kk + tig];
            uint32_t a2 = Ps[(wr + g) * 68 + kk + tig + 4];
            uint32_t a3 = Ps[(wr + g + 8) * 68 + kk + tig + 4];
#pragma unroll
            for (int nt = 0; nt < 8; nt++) {
                uint32_t b0 = Vs[(kk + tig) * 72 + nt * 8 + g];
                uint32_t b1 = Vs[(kk + tig + 4) * 72 + nt * 8 + g];
                mma_tf32(oacc[nt], a0, a1, a2, a3, b0, b1);
            }
        }
    }

    // normalize + tf32-round + write [b][s][h][d] (feeds Wo GEMM raw)
    float inv0 = 1.f / l0, inv1 = 1.f / l1;
    int sg0 = qt * 128 + wr + g, sg1 = sg0 + 8;
#pragma unroll
    for (int nt = 0; nt < 8; nt++) {
        int d = nt * 8 + 2 * tig;
        float2 o0 = make_float2(f2tff(oacc[nt][0] * inv0), f2tff(oacc[nt][1] * inv0));
        float2 o1 = make_float2(f2tff(oacc[nt][2] * inv1), f2tff(oacc[nt][3] * inv1));
        *(float2*)&gO[(((size_t)b * SEQ + sg0) * NH + h) * DK + d] = o0;
        *(float2*)&gO[(((size_t)b * SEQ + sg1) * NH + h) * DK + d] = o1;
    }
}

// ---------------- launch ----------------
extern "C" void kernel_launch(void* const* d_in, const int* in_sizes, int n_in,
                              void* d_out, int out_size) {
    const float* x = (const float*)d_in[0];
    const int* tpos = (const int*)d_in[1];
    const float* Wq = (const float*)d_in[2];
    const float* Wk = (const float*)d_in[3];
    const float* Wv = (const float*)d_in[4];
    const float* Wo = (const float*)d_in[5];
    float* out = (float*)d_out;

    float *gQ, *gK, *gV, *gA, *gXr, *gWr;
    cudaGetSymbolAddress((void**)&gQ, g_Q);
    cudaGetSymbolAddress((void**)&gK, g_K);
    cudaGetSymbolAddress((void**)&gV, g_V);
    cudaGetSymbolAddress((void**)&gA, g_A);
    cudaGetSymbolAddress((void**)&gXr, g_Xr);
    cudaGetSymbolAddress((void**)&gWr, g_Wr);

    cudaFuncSetAttribute(gemm_mma<1>, cudaFuncAttributeMaxDynamicSharedMemorySize,
                         GEMM_SMEM);
    cudaFuncSetAttribute(gemm_mma<0>, cudaFuncAttributeMaxDynamicSharedMemorySize,
                         GEMM_SMEM);
    cudaFuncSetAttribute(attn_tf32, cudaFuncAttributeMaxDynamicSharedMemorySize,
                         ATT_SMEM);

    // 1) round x + all W to tf32 once
    round_tf32_kernel<<<12288, 256>>>(x, Wq, Wk, Wv, Wo);

    // 2) Q/K/V projections (grid.z selects weight/dst); tf32-rounded out
    gemm_mma<1><<<dim3(8, 64, 3), 256, GEMM_SMEM>>>(gXr, gWr, gQ, gK, gV);

    // 3) RoPE (folds Q-scale, rounds to tf32)
    const int NPAIR = BATCH * NH * SEQ * (DK / 2);
    rope_kernel<<<dim3((NPAIR + 255) / 256, 2), 256>>>(gQ, gK, tpos);

    // 4) attention (Br=128; consumes raw tf32 bits; writes tf32-rounded gA)
    attn_tf32<<<dim3(SEQ / 128, NH, BATCH), 256, ATT_SMEM>>>(gQ, gK, gV, gA);

    // 5) output projection (fp32 result)
    gemm_mma<0><<<dim3(8, 64, 1), 256, GEMM_SMEM>>>(gA, gWr + (size_t)3 * DM * DM,
                                                    out, out, out);
}

// round 8
// speedup vs baseline: 3.0508x; 3.0508x over previous
#include <cuda_runtime.h>
#include <cuda_fp16.h>
#include <cstdint>

#define BATCH 2
#define SEQ 4096
#define NH 16
#define DK 64
#define DM 1024
#define L2E 1.4426950408889634f

#define QKV_ELEMS ((size_t)BATCH * NH * SEQ * DK)

// ---------------- scratch (no allocation allowed) ----------------
__device__ unsigned short g_Qh[QKV_ELEMS];
__device__ unsigned short g_Kh[QKV_ELEMS];
__device__ unsigned short g_Vh[QKV_ELEMS];
__device__ unsigned short g_Ah[(size_t)BATCH * SEQ * DM];
__device__ unsigned short g_Xh[(size_t)BATCH * SEQ * DM];
__device__ unsigned short g_Wh[(size_t)4 * DM * DM];

// ---------------- helpers ----------------
__device__ __forceinline__ uint32_t pkh(float lo, float hi) {
    uint32_t r;
    asm("cvt.rn.f16x2.f32 %0, %1, %2;" : "=r"(r) : "f"(hi), "f"(lo));
    return r;
}
__device__ __forceinline__ uint32_t smem_u32(const void* p) {
    uint32_t a;
    asm("{ .reg .u64 t; cvta.to.shared.u64 t, %1; cvt.u32.u64 %0, t; }"
        : "=r"(a) : "l"(p));
    return a;
}
__device__ __forceinline__ void cp16(uint32_t dst, const void* src) {
    asm volatile("cp.async.cg.shared.global [%0], [%1], 16;" :: "r"(dst), "l"(src));
}
__device__ __forceinline__ void cp_commit() {
    asm volatile("cp.async.commit_group;" ::: "memory");
}
template <int N>
__device__ __forceinline__ void cp_wait() {
    asm volatile("cp.async.wait_group %0;" :: "n"(N) : "memory");
}
__device__ __forceinline__ void ldsm4(uint32_t& r0, uint32_t& r1, uint32_t& r2,
                                      uint32_t& r3, uint32_t a) {
    asm volatile("ldmatrix.sync.aligned.m8n8.x4.shared.b16 {%0,%1,%2,%3}, [%4];"
                 : "=r"(r0), "=r"(r1), "=r"(r2), "=r"(r3) : "r"(a));
}
__device__ __forceinline__ void ldsm4t(uint32_t& r0, uint32_t& r1, uint32_t& r2,
                                       uint32_t& r3, uint32_t a) {
    asm volatile("ldmatrix.sync.aligned.m8n8.x4.trans.shared.b16 {%0,%1,%2,%3}, [%4];"
                 : "=r"(r0), "=r"(r1), "=r"(r2), "=r"(r3) : "r"(a));
}
__device__ __forceinline__ void mma16(float c[4], uint32_t a0, uint32_t a1,
                                      uint32_t a2, uint32_t a3,
                                      uint32_t b0, uint32_t b1) {
    asm volatile(
        "mma.sync.aligned.m16n8k16.row.col.f32.f16.f16.f32 "
        "{%0,%1,%2,%3}, {%4,%5,%6,%7}, {%8,%9}, {%0,%1,%2,%3};"
        : "+f"(c[0]), "+f"(c[1]), "+f"(c[2]), "+f"(c[3])
        : "r"(a0), "r"(a1), "r"(a2), "r"(a3), "r"(b0), "r"(b1));
}

// ---------------- convert x + all W to fp16 ----------------
__global__ __launch_bounds__(256) void round_f16_kernel(
    const float* __restrict__ x, const float* __restrict__ Wq,
    const float* __restrict__ Wk, const float* __restrict__ Wv,
    const float* __restrict__ Wo) {
    size_t i4 = (size_t)blockIdx.x * 256 + threadIdx.x;  // float4 index
    const float4* src;
    uint2* dst;
    if (i4 < 2097152) {
        src = (const float4*)x + i4;
        dst = (uint2*)g_Xh + i4;
    } else {
        size_t r = i4 - 2097152;
        int j = (int)(r >> 18);
        size_t o = r & 262143;
        const float* w = (j == 0) ? Wq : (j == 1) ? Wk : (j == 2) ? Wv : Wo;
        src = (const float4*)w + o;
        dst = (uint2*)g_Wh + (size_t)j * 262144 + o;
    }
    float4 v = *src;
    *dst = make_uint2(pkh(v.x, v.y), pkh(v.z, v.w));
}

// ---------------- fp16 mma GEMM: C = A(Mx1024) * W(1024x1024)^T ------------
// tile 128x128, k-block 32, 2-stage cp.async, ldmatrix operands.
// smem per stage: A 128x40 fp16 (10240B) + W 128x40 (10240B).
// MODE 0: fp32 row-major C.  MODE 1: fp16 scatter [b][h][s][64] (dst by z).
#define GSTAGE 20480
#define GEMM_SMEM (2 * GSTAGE)

template <int MODE>
__global__ __launch_bounds__(256, 2) void gemm_f16(
    const unsigned short* __restrict__ Abase,
    const unsigned short* __restrict__ Wbase,
    void* C0, void* C1, void* C2) {
    extern __shared__ __align__(16) char smraw[];
    const uint32_t smb = smem_u32(smraw);

    const int tid = threadIdx.x, wid = tid >> 5, lane = tid & 31;
    const int g = lane >> 2, tig = lane & 3;
    const int wm = (wid & 1) * 64, wn = (wid >> 1) * 32;
    const int z = blockIdx.z;
    const int m0 = blockIdx.y * 128, n0 = blockIdx.x * 128;
    const unsigned short* W = Wbase + (size_t)z * (DM * DM);
    void* C = (z == 0) ? C0 : (z == 1) ? C1 : C2;

    float acc[4][4][4];
#pragma unroll
    for (int mt = 0; mt < 4; mt++)
#pragma unroll
        for (int nt = 0; nt < 4; nt++)
#pragma unroll
            for (int k = 0; k < 4; k++) acc[mt][nt][k] = 0.f;

    // ldmatrix source addresses (per-lane, per warp-tile)
    const int a_r = (lane & 7) + ((lane >> 3) & 1) * 8;   // row within 16-block
    const int a_c = (lane >> 4) << 3;                     // k offset 0/8

    const int lr2 = tid >> 2, lc2 = (tid & 3) * 8;        // fill indexing

    auto fill = [&](int s) {
        const uint32_t st = smb + (uint32_t)(s & 1) * GSTAGE;
        const int kb = s * 32;
#pragma unroll
        for (int i = 0; i < 2; i++) {
            int r = lr2 + i * 64;
            cp16(st + r * 80 + (lc2 >> 3) * 16,
                 Abase + (size_t)(m0 + r) * DM + kb + lc2);
        }
#pragma unroll
        for (int i = 0; i < 2; i++) {
            int r = lr2 + i * 64;
            cp16(st + 10240 + r * 80 + (lc2 >> 3) * 16,
                 W + (size_t)(n0 + r) * DM + kb + lc2);
        }
        cp_commit();
    };

    fill(0);

    for (int s = 0; s < 32; s++) {
        if (s + 1 < 32) {
            fill(s + 1);
            cp_wait<1>();
        } else {
            cp_wait<0>();
        }
        __syncthreads();
        const uint32_t asb = smb + (uint32_t)(s & 1) * GSTAGE;
        const uint32_t wsb = asb + 10240;

#pragma unroll
        for (int kk = 0; kk < 32; kk += 16) {
            uint32_t a[4][4], b[2][4];
#pragma unroll
            for (int mt = 0; mt < 4; mt++) {
                int ar = wm + mt * 16 + a_r;
                ldsm4(a[mt][0], a[mt][1], a[mt][2], a[mt][3],
                      asb + (uint32_t)(ar * 40 + kk + a_c) * 2);
            }
#pragma unroll
            for (int j = 0; j < 2; j++) {
                int nr = wn + j * 16 + (lane & 7) + ((lane >> 4) << 3);
                int kc = kk + ((lane >> 3) & 1) * 8;
                ldsm4(b[j][0], b[j][1], b[j][2], b[j][3],
                      wsb + (uint32_t)(nr * 40 + kc) * 2);
            }
#pragma unroll
            for (int mt = 0; mt < 4; mt++)
#pragma unroll
                for (int j = 0; j < 2; j++) {
                    mma16(acc[mt][2 * j], a[mt][0], a[mt][1], a[mt][2], a[mt][3],
                          b[j][0], b[j][1]);
                    mma16(acc[mt][2 * j + 1], a[mt][0], a[mt][1], a[mt][2], a[mt][3],
                          b[j][2], b[j][3]);
                }
        }
        __syncthreads();
    }

#pragma unroll
    for (int mt = 0; mt < 4; mt++) {
#pragma unroll
        for (int nt = 0; nt < 4; nt++) {
            int r0 = m0 + wm + mt * 16 + g;
            int r1 = r0 + 8;
            int cc = n0 + wn + nt * 8 + 2 * tig;
            if (MODE == 0) {
                float* Cf = (float*)C;
                *(float2*)&Cf[(size_t)r0 * DM + cc] =
                    make_float2(acc[mt][nt][0], acc[mt][nt][1]);
                *(float2*)&Cf[(size_t)r1 * DM + cc] =
                    make_float2(acc[mt][nt][2], acc[mt][nt][3]);
            } else {
                unsigned short* Ch = (unsigned short*)C;
                int h = cc >> 6, d = cc & 63;
                int b0i = r0 >> 12, s0 = r0 & (SEQ - 1);
                int b1i = r1 >> 12, s1 = r1 & (SEQ - 1);
                *(uint32_t*)(Ch + ((size_t)(b0i * NH + h) * SEQ + s0) * DK + d) =
                    pkh(acc[mt][nt][0], acc[mt][nt][1]);
                *(uint32_t*)(Ch + ((size_t)(b1i * NH + h) * SEQ + s1) * DK + d) =
                    pkh(acc[mt][nt][2], acc[mt][nt][3]);
            }
        }
    }
}

// ---------------- RoPE (fp16 in-place; folds Q-scale) ----------------
__global__ void rope_kernel(const int* __restrict__ pos) {
    const int NPAIR = BATCH * NH * SEQ * (DK / 2);
    int i = blockIdx.x * blockDim.x + threadIdx.x;
    if (i >= NPAIR) return;
    int j = i & 31;
    int s = (i >> 5) & (SEQ - 1);
    int h = (i >> 17) & (NH - 1);
    int b = i >> 21;

    const bool isQ = (blockIdx.y == 0);
    uint32_t* ptr32 = (uint32_t*)(isQ ? g_Qh : g_Kh);
    int p = pos[b * SEQ + s];
    float freq = exp2f(-(float)j * (13.287712379549449f / 32.f));
    float ang = (float)p * freq;
    float sn, cs;
    sincosf(ang, &sn, &cs);

    size_t idx = ((size_t)(b * NH + h) * SEQ + s) * 32 + j;
    uint32_t pv = ptr32[idx];
    __half2 hv = *(__half2*)&pv;
    float e = __half2float(__low2half(hv));
    float o = __half2float(__high2half(hv));
    float ne = e * cs - o * sn;
    float no = e * sn + o * cs;
    if (isQ) {
        const float qscale = 0.125f * L2E;
        ne *= qscale;
        no *= qscale;
    }
    ptr32[idx] = pkh(ne, no);
}

// ---------------- causal flash attention, fp16 mma + ldmatrix --------------
// Br=Bc=64, 128 threads (4 warps x 16 rows). Q frags in registers.
// smem bytes: Qs[64x72h]=9216 | Ks x2 | Vs x2  -> 46080 total.
#define AQ_OFF 0
#define AK_OFF 9216
#define AV_OFF (9216 + 2 * 9216)
#define ATT_SMEM (9216 * 5)

__global__ __launch_bounds__(128) void attn_f16(float* dummy) {
    extern __shared__ __align__(16) char asm_raw[];
    const uint32_t smb = smem_u32(asm_raw);

    const int qt = 63 - (int)blockIdx.x;
    const int h = blockIdx.y;
    const int b = blockIdx.z;
    const int tid = threadIdx.x;
    const int wid = tid >> 5, lane = tid & 31;
    const int g = lane >> 2, tig = lane & 3;
    const int wr = wid * 16;

    const size_t bh = (size_t)(b * NH + h) * SEQ;
    const unsigned short* Qb = g_Qh + (bh + (size_t)qt * 64) * DK;
    const unsigned short* Kb = g_Kh + bh * DK;
    const unsigned short* Vb = g_Vh + bh * DK;

    // ldmatrix lane geometry
    const int l_r = (lane & 7) + ((lane >> 3) & 1) * 8;
    const int l_c8 = (lane >> 4) << 3;

    // prefetch K/V tile kt into buffer buf
    auto prefetch = [&](int kt, int buf) {
        const uint32_t kst = smb + AK_OFF + buf * 9216;
        const uint32_t vst = smb + AV_OFF + buf * 9216;
#pragma unroll
        for (int i = 0; i < 4; i++) {
            int q = tid + i * 128;
            int r = q >> 3, c = q & 7;
            cp16(kst + r * 144 + c * 16, Kb + (size_t)(kt * 64 + r) * DK + c * 8);
        }
#pragma unroll
        for (int i = 0; i < 4; i++) {
            int q = tid + i * 128;
            int r = q >> 3, c = q & 7;
            cp16(vst + r * 144 + c * 16, Vb + (size_t)(kt * 64 + r) * DK + c * 8);
        }
        cp_commit();
    };

    // Q tile -> smem (synchronous; once)
#pragma unroll
    for (int p = 0; p < 4; p++) {
        int idx = p * 128 + tid;
        int r = idx >> 3, c = idx & 7;
        *(uint4*)(asm_raw + r * 144 + c * 16) =
            *(const uint4*)(Qb + (size_t)r * DK + c * 8);
    }
    prefetch(0, 0);
    __syncthreads();

    // hoist Q fragments (4 k-chunks of 16)
    uint32_t qf[4][4];
#pragma unroll
    for (int kq = 0; kq < 4; kq++) {
        int qr = wr + l_r;
        int qc = kq * 16 + l_c8;
        ldsm4(qf[kq][0], qf[kq][1], qf[kq][2], qf[kq][3],
              smb + (uint32_t)(qr * 72 + qc) * 2);
    }

    float oacc[8][4];
    float m0 = -1e30f, m1 = -1e30f, l0 = 0.f, l1 = 0.f;
#pragma unroll
    for (int nt = 0; nt < 8; nt++)
#pragma unroll
        for (int k = 0; k < 4; k++) oacc[nt][k] = 0.f;

    const int ntiles = qt + 1;
    for (int kt = 0; kt < ntiles; kt++) {
        const int buf = kt & 1;
        __syncthreads();
        if (kt + 1 < ntiles) {
            prefetch(kt + 1, buf ^ 1);
            cp_wait<1>();
        } else {
            cp_wait<0>();
        }
        __syncthreads();

        const uint32_t ksb = smb + AK_OFF + buf * 9216;
        const uint32_t vsb = smb + AV_OFF + buf * 9216;

        // S = Q K^T
        float sacc[8][4];
#pragma unroll
        for (int nt = 0; nt < 8; nt++)
#pragma unroll
            for (int k = 0; k < 4; k++) sacc[nt][k] = 0.f;

#pragma unroll
        for (int kq = 0; kq < 4; kq++) {
            const int kk = kq * 16;
#pragma unroll
            for (int j = 0; j < 4; j++) {
                int nr = j * 16 + (lane & 7) + l_c8;
                int kc = kk + ((lane >> 3) & 1) * 8;
                uint32_t b0, b1, b2, b3;
                ldsm4(b0, b1, b2, b3, ksb + (uint32_t)(nr * 72 + kc) * 2);
                mma16(sacc[2 * j], qf[kq][0], qf[kq][1], qf[kq][2], qf[kq][3], b0, b1);
                mma16(sacc[2 * j + 1], qf[kq][0], qf[kq][1], qf[kq][2], qf[kq][3], b2, b3);
            }
        }

        if (kt == qt) {  // causal mask on diagonal tile
#pragma unroll
            for (int nt = 0; nt < 8; nt++) {
                int c0 = nt * 8 + 2 * tig, c1 = c0 + 1;
                if (c0 > wr + g) sacc[nt][0] = -1e30f;
                if (c1 > wr + g) sacc[nt][1] = -1e30f;
                if (c0 > wr + g + 8) sacc[nt][2] = -1e30f;
                if (c1 > wr + g + 8) sacc[nt][3] = -1e30f;
            }
        }

        // online softmax (rows wr+g, wr+g+8)
        float tm0 = -1e30f, tm1 = -1e30f;
#pragma unroll
        for (int nt = 0; nt < 8; nt++) {
            tm0 = fmaxf(tm0, fmaxf(sacc[nt][0], sacc[nt][1]));
            tm1 = fmaxf(tm1, fmaxf(sacc[nt][2], sacc[nt][3]));
        }
        tm0 = fmaxf(tm0, __shfl_xor_sync(0xffffffffu, tm0, 1));
        tm0 = fmaxf(tm0, __shfl_xor_sync(0xffffffffu, tm0, 2));
        tm1 = fmaxf(tm1, __shfl_xor_sync(0xffffffffu, tm1, 1));
        tm1 = fmaxf(tm1, __shfl_xor_sync(0xffffffffu, tm1, 2));

        float mn0 = fmaxf(m0, tm0), mn1 = fmaxf(m1, tm1);
        float al0 = exp2f(m0 - mn0), al1 = exp2f(m1 - mn1);
        m0 = mn0; m1 = mn1;

        float rs0 = 0.f, rs1 = 0.f;
#pragma unroll
        for (int nt = 0; nt < 8; nt++) {
            sacc[nt][0] = exp2f(sacc[nt][0] - mn0);
            sacc[nt][1] = exp2f(sacc[nt][1] - mn0);
            sacc[nt][2] = exp2f(sacc[nt][2] - mn1);
            sacc[nt][3] = exp2f(sacc[nt][3] - mn1);
            rs0 += sacc[nt][0] + sacc[nt][1];
            rs1 += sacc[nt][2] + sacc[nt][3];
        }
        rs0 += __shfl_xor_sync(0xffffffffu, rs0, 1);
        rs0 += __shfl_xor_sync(0xffffffffu, rs0, 2);
        rs1 += __shfl_xor_sync(0xffffffffu, rs1, 1);
        rs1 += __shfl_xor_sync(0xffffffffu, rs1, 2);
        l0 = l0 * al0 + rs0;
        l1 = l1 * al1 + rs1;

#pragma unroll
        for (int nt = 0; nt < 8; nt++) {
            oacc[nt][0] *= al0; oacc[nt][1] *= al0;
            oacc[nt][2] *= al1; oacc[nt][3] *= al1;
        }

        // O += P V : P direct from registers (fp16), V via ldmatrix.trans
#pragma unroll
        for (int kc = 0; kc < 64; kc += 16) {
            const int e = kc >> 3;
            uint32_t a0 = pkh(sacc[e][0], sacc[e][1]);
            uint32_t a1 = pkh(sacc[e][2], sacc[e][3]);
            uint32_t a2 = pkh(sacc[e + 1][0], sacc[e + 1][1]);
            uint32_t a3 = pkh(sacc[e + 1][2], sacc[e + 1][3]);
#pragma unroll
            for (int j = 0; j < 4; j++) {
                int vr = kc + l_r;
                int vc = j * 16 + l_c8;
                uint32_t b0, b1, b2, b3;
                ldsm4t(b0, b1, b2, b3, vsb + (uint32_t)(vr * 72 + vc) * 2);
                mma16(oacc[2 * j], a0, a1, a2, a3, b0, b1);
                mma16(oacc[2 * j + 1], a0, a1, a2, a3, b2, b3);
            }
        }
    }

    // normalize + fp16 write [b][s][h][d] (feeds Wo GEMM)
    float inv0 = 1.f / l0, inv1 = 1.f / l1;
    int sg0 = qt * 64 + wr + g, sg1 = sg0 + 8;
#pragma unroll
    for (int nt = 0; nt < 8; nt++) {
        int d = nt * 8 + 2 * tig;
        *(uint32_t*)(g_Ah + (((size_t)b * SEQ + sg0) * NH + h) * DK + d) =
            pkh(oacc[nt][0] * inv0, oacc[nt][1] * inv0);
        *(uint32_t*)(g_Ah + (((size_t)b * SEQ + sg1) * NH + h) * DK + d) =
            pkh(oacc[nt][2] * inv1, oacc[nt][3] * inv1);
    }
    (void)dummy;
}

// ---------------- launch ----------------
extern "C" void kernel_launch(void* const* d_in, const int* in_sizes, int n_in,
                              void* d_out, int out_size) {
    const float* x = (const float*)d_in[0];
    const int* tpos = (const int*)d_in[1];
    const float* Wq = (const float*)d_in[2];
    const float* Wk = (const float*)d_in[3];
    const float* Wv = (const float*)d_in[4];
    const float* Wo = (const float*)d_in[5];
    float* out = (float*)d_out;

    unsigned short *gQ, *gK, *gV, *gA, *gX, *gW;
    cudaGetSymbolAddress((void**)&gQ, g_Qh);
    cudaGetSymbolAddress((void**)&gK, g_Kh);
    cudaGetSymbolAddress((void**)&gV, g_Vh);
    cudaGetSymbolAddress((void**)&gA, g_Ah);
    cudaGetSymbolAddress((void**)&gX, g_Xh);
    cudaGetSymbolAddress((void**)&gW, g_Wh);

    cudaFuncSetAttribute(gemm_f16<1>, cudaFuncAttributeMaxDynamicSharedMemorySize,
                         GEMM_SMEM);
    cudaFuncSetAttribute(gemm_f16<0>, cudaFuncAttributeMaxDynamicSharedMemorySize,
                         GEMM_SMEM);
    cudaFuncSetAttribute(attn_f16, cudaFuncAttributeMaxDynamicSharedMemorySize,
                         ATT_SMEM);

    // 1) convert x + all W to fp16
    round_f16_kernel<<<12288, 256>>>(x, Wq, Wk, Wv, Wo);

    // 2) Q/K/V projections (grid.z selects weight/dst); fp16 out
    gemm_f16<1><<<dim3(8, 64, 3), 256, GEMM_SMEM>>>(gX, gW, gQ, gK, gV);

    // 3) RoPE (folds Q-scale)
    const int NPAIR = BATCH * NH * SEQ * (DK / 2);
    rope_kernel<<<dim3((NPAIR + 255) / 256, 2), 256>>>(tpos);

    // 4) attention (fp16, ldmatrix, register-P)
    attn_f16<<<dim3(SEQ / 64, NH, BATCH), 128, ATT_SMEM>>>(nullptr);

    // 5) output projection (fp32 result)
    gemm_f16<0><<<dim3(8, 64, 1), 256, GEMM_SMEM>>>(gA, gW + (size_t)3 * DM * DM,
                                                    out, out, out);
}